// round 14
// baseline (speedup 1.0000x reference)
#include <cuda_runtime.h>
#include <cuda_fp16.h>
#include <math.h>
#include <stdint.h>

#define NEXP   8
#define TOKENS 2048
#define NEMBD  1024
#define DFF    4096

// ---------------- device scratch (no runtime allocation) ----------------
__device__ __half g_x16[(size_t)NEXP * TOKENS * NEMBD];
__device__ __half g_w1[(size_t)NEXP * DFF * NEMBD];   // [e][N=DFF][K=NEMBD]
__device__ __half g_w2[(size_t)NEXP * NEMBD * DFF];   // [e][N=NEMBD][K=DFF]
__device__ __half g_h16[(size_t)NEXP * TOKENS * DFF]; // hidden (post-GELU)

// ---------------- helpers ----------------
__device__ __forceinline__ uint32_t smem_to_u32(const void* p) {
    uint32_t a;
    asm("{ .reg .u64 t; cvta.to.shared.u64 t, %1; cvt.u32.u64 %0, t; }" : "=r"(a) : "l"(p));
    return a;
}
__device__ __forceinline__ void cp_async16(uint32_t saddr, const void* gaddr) {
    asm volatile("cp.async.cg.shared.global [%0], [%1], 16;" :: "r"(saddr), "l"(gaddr));
}
#define CP_COMMIT() asm volatile("cp.async.commit_group;" ::: "memory")
#define CP_WAIT(n)  asm volatile("cp.async.wait_group %0;" :: "n"(n) : "memory")

__device__ __forceinline__ void ldsm_x4(uint32_t* r, uint32_t addr) {
    asm volatile("ldmatrix.sync.aligned.m8n8.x4.shared.b16 {%0,%1,%2,%3}, [%4];"
        : "=r"(r[0]), "=r"(r[1]), "=r"(r[2]), "=r"(r[3]) : "r"(addr));
}
__device__ __forceinline__ void mma_fp16(float* d, const uint32_t* a, const uint32_t* b) {
    asm volatile(
        "mma.sync.aligned.m16n8k16.row.col.f32.f16.f16.f32 "
        "{%0,%1,%2,%3}, {%4,%5,%6,%7}, {%8,%9}, {%0,%1,%2,%3};"
        : "+f"(d[0]), "+f"(d[1]), "+f"(d[2]), "+f"(d[3])
        : "r"(a[0]), "r"(a[1]), "r"(a[2]), "r"(a[3]), "r"(b[0]), "r"(b[1]));
}

__device__ __forceinline__ float gelu_exact(float x) {
    return 0.5f * x * (1.0f + erff(x * 0.70710678118654752440f));
}

// ---------------- pre-pass: convert x -> fp16 ----------------
__global__ __launch_bounds__(256) void conv_x(const float* __restrict__ x) {
    const size_t n4 = (size_t)NEXP * TOKENS * NEMBD / 4;
    const float4* in = reinterpret_cast<const float4*>(x);
    for (size_t i = blockIdx.x * 256ull + threadIdx.x; i < n4; i += (size_t)gridDim.x * 256) {
        float4 v = in[i];
        __half2 a = __halves2half2(__float2half_rn(v.x), __float2half_rn(v.y));
        __half2 b = __halves2half2(__float2half_rn(v.z), __float2half_rn(v.w));
        reinterpret_cast<uint2*>(g_x16)[i] =
            make_uint2(*reinterpret_cast<uint32_t*>(&a), *reinterpret_cast<uint32_t*>(&b));
    }
}

// ---------------- pre-pass: convert + transpose weights ----------------
template<int W>
__global__ __launch_bounds__(256) void conv_transpose(const float* __restrict__ in) {
    constexpr int R = (W == 1) ? NEMBD : DFF;
    constexpr int C = (W == 1) ? DFF : NEMBD;
    __half* oh = (W == 1) ? g_w1 : g_w2;
    __shared__ float t[32][33];
    const int e = blockIdx.z;
    const float* src = in + (size_t)e * R * C;
    __half* dh = oh + (size_t)e * R * C;
    const int c0 = blockIdx.x * 32, r0 = blockIdx.y * 32;
    const int tx = threadIdx.x & 31, ty = threadIdx.x >> 5;   // 32 x 8
    #pragma unroll
    for (int j = 0; j < 4; ++j)
        t[ty + j * 8][tx] = src[(size_t)(r0 + ty + j * 8) * C + c0 + tx];
    __syncthreads();
    #pragma unroll
    for (int j = 0; j < 4; ++j) {
        float v = t[tx][ty + j * 8];                     // in[r0+tx][c0+ty+j*8]
        size_t o = (size_t)(c0 + ty + j * 8) * R + r0 + tx;
        dh[o] = __float2half_rn(v);
    }
}

// ---------------- mma.sync grouped GEMM, plain fp16 ----------------
// CTA tile 128(m) x 128(n), BK=64, 256 threads = 8 warps as 2(m) x 4(n),
// warp tile 64x32. 3-stage cp.async pipeline, 2 CTAs/SM.
// Odd warps walk ks in rotated order to de-phase LDSM bursts.
template<bool DO_GELU>
__global__ __launch_bounds__(256, 2) void gemm_mma(const float* __restrict__ bias_all,
                                                   float* __restrict__ Cf) {
    constexpr int M = TOKENS;
    constexpr int N = DO_GELU ? DFF : NEMBD;
    constexpr int K = DO_GELU ? NEMBD : DFF;
    constexpr int NC = K / 64;             // k-chunks of 64
    constexpr int ROWB = 144;              // bytes per smem row (64 fp16 + 16 pad)
    constexpr int A_TILE = 128 * ROWB;     // 18432
    constexpr int B_TILE = 128 * ROWB;     // 18432
    constexpr int STAGE = A_TILE + B_TILE; // 36864
    constexpr int NSTAGE = 3;

    const __half* Abase = DO_GELU ? g_x16 : g_h16;
    const __half* Bbase = DO_GELU ? g_w1 : g_w2;

    extern __shared__ __align__(1024) char smem[];
    const uint32_t sbase = smem_to_u32(smem);

    const int tid = threadIdx.x;
    const int wid = tid >> 5, lane = tid & 31;
    const int e = blockIdx.z;
    const int m0 = blockIdx.y * 128, n0 = blockIdx.x * 128;

    const __half* A = Abase + (size_t)e * M * K;
    const __half* B = Bbase + (size_t)e * N * K;
    const float* bias = bias_all + (size_t)e * N;

    // warp tile: 64(m) x 32(n); warps arranged 2(m) x 4(n)
    const int wm = (wid >> 2) * 64;
    const int wn = (wid & 3) * 32;
    // per-warp ks phase rotation (0 or 2)
    const uint32_t ks_rot = (uint32_t)((wid & 1) << 1);

    float acc[4][4][4];
    #pragma unroll
    for (int i = 0; i < 4; ++i)
        #pragma unroll
        for (int j = 0; j < 4; ++j)
            #pragma unroll
            for (int q = 0; q < 4; ++q) acc[i][j][q] = 0.0f;

    // ---- hoisted loader state ----
    const uint32_t l_row = (uint32_t)tid >> 3;       // 0..31
    const uint32_t l_ch  = (uint32_t)tid & 7;        // 0..7
    const uint32_t l_so  = l_row * ROWB + l_ch * 16; // smem offset within tile
    const __half* aptr[4];
    const __half* bptr[4];
    #pragma unroll
    for (int it = 0; it < 4; ++it) {
        aptr[it] = A + (size_t)(m0 + l_row + it * 32) * K + l_ch * 8;
        bptr[it] = B + (size_t)(n0 + l_row + it * 32) * K + l_ch * 8;
    }

    auto load_stage = [&](int s) {
        const uint32_t sb = sbase + s * STAGE;
        #pragma unroll
        for (int it = 0; it < 4; ++it)
            cp_async16(sb + l_so + (uint32_t)(it * 32 * ROWB), aptr[it]);
        #pragma unroll
        for (int it = 0; it < 4; ++it)
            cp_async16(sb + A_TILE + l_so + (uint32_t)(it * 32 * ROWB), bptr[it]);
        CP_COMMIT();
        #pragma unroll
        for (int it = 0; it < 4; ++it) { aptr[it] += 64; bptr[it] += 64; }
    };

    load_stage(0);
    load_stage(1);

    // per-lane ldmatrix address components
    const uint32_t a_off = (uint32_t)((wm + (lane & 15)) * ROWB + (lane >> 4) * 16);
    const uint32_t b_off = (uint32_t)((wn + (lane & 7) + ((lane >> 4) << 3)) * ROWB + ((lane >> 3) & 1) * 16);

    #pragma unroll 3
    for (int c = 0; c < NC; ++c) {
        if (c + 1 < NC) { CP_WAIT(1); } else { CP_WAIT(0); }
        __syncthreads();
        if (c + 2 < NC) load_stage((c + 2) % NSTAGE);

        const uint32_t sb = sbase + (c % NSTAGE) * STAGE;
        #pragma unroll
        for (int ksi = 0; ksi < 4; ++ksi) {
            const uint32_t kso = ((ksi + ks_rot) & 3) * 32;
            uint32_t bf[2][4];
            #pragma unroll
            for (int nt2 = 0; nt2 < 2; ++nt2)
                ldsm_x4(bf[nt2], sb + A_TILE + b_off + kso + (uint32_t)(nt2 * 16 * ROWB));
            // A-fragment double buffer across mt (branch-free prologue form)
            uint32_t af[2][4];
            ldsm_x4(af[0], sb + a_off + kso);
            #pragma unroll
            for (int mt = 0; mt < 3; ++mt) {
                ldsm_x4(af[(mt + 1) & 1], sb + a_off + kso + (uint32_t)((mt + 1) * 16 * ROWB));
                #pragma unroll
                for (int nt = 0; nt < 4; ++nt)
                    mma_fp16(acc[mt][nt], af[mt & 1], &bf[nt >> 1][(nt & 1) * 2]);
            }
            #pragma unroll
            for (int nt = 0; nt < 4; ++nt)
                mma_fp16(acc[3][nt], af[1], &bf[nt >> 1][(nt & 1) * 2]);
        }
    }

    // ---------------- epilogue ----------------
    const int groupID = lane >> 2, tig = lane & 3;
    #pragma unroll
    for (int mt = 0; mt < 4; ++mt) {
        const int r0g = m0 + wm + mt * 16 + groupID;
        #pragma unroll
        for (int nt = 0; nt < 4; ++nt) {
            const int col = n0 + wn + nt * 8 + tig * 2;
            const float2 bv = *reinterpret_cast<const float2*>(&bias[col]);
            float v0 = acc[mt][nt][0] + bv.x;
            float v1 = acc[mt][nt][1] + bv.y;
            float v2 = acc[mt][nt][2] + bv.x;
            float v3 = acc[mt][nt][3] + bv.y;
            if (DO_GELU) {
                v0 = gelu_exact(v0); v1 = gelu_exact(v1);
                v2 = gelu_exact(v2); v3 = gelu_exact(v3);
                const size_t o0 = ((size_t)e * M + r0g) * N + col;
                const size_t o1 = ((size_t)e * M + r0g + 8) * N + col;
                *reinterpret_cast<__half2*>(g_h16 + o0) =
                    __halves2half2(__float2half_rn(v0), __float2half_rn(v1));
                *reinterpret_cast<__half2*>(g_h16 + o1) =
                    __halves2half2(__float2half_rn(v2), __float2half_rn(v3));
            } else {
                const size_t o0 = ((size_t)e * M + r0g) * N + col;
                const size_t o1 = ((size_t)e * M + r0g + 8) * N + col;
                *reinterpret_cast<float2*>(Cf + o0) = make_float2(v0, v1);
                *reinterpret_cast<float2*>(Cf + o1) = make_float2(v2, v3);
            }
        }
    }
}

// ---------------- launch ----------------
extern "C" void kernel_launch(void* const* d_in, const int* in_sizes, int n_in,
                              void* d_out, int out_size) {
    const float* x         = (const float*)d_in[0];
    const float* c_fc      = (const float*)d_in[1];
    const float* c_proj    = (const float*)d_in[2];
    const float* fc_bias   = (const float*)d_in[3];
    const float* proj_bias = (const float*)d_in[4];
    float* out = (float*)d_out;

    constexpr int SMEM_BYTES = 3 * 36864;   // 110592 per CTA, 2 CTAs/SM
    cudaFuncSetAttribute(gemm_mma<true>,  cudaFuncAttributeMaxDynamicSharedMemorySize, SMEM_BYTES);
    cudaFuncSetAttribute(gemm_mma<false>, cudaFuncAttributeMaxDynamicSharedMemorySize, SMEM_BYTES);

    // pre-passes
    conv_x<<<4096, 256>>>(x);
    conv_transpose<1><<<dim3(DFF / 32, NEMBD / 32, NEXP), 256>>>(c_fc);
    conv_transpose<2><<<dim3(NEMBD / 32, DFF / 32, NEXP), 256>>>(c_proj);

    // GEMM1: [2048,1024] @ [1024,4096] + b1, gelu -> h (fp16)
    gemm_mma<true><<<dim3(DFF / 128, TOKENS / 128, NEXP), 256, SMEM_BYTES>>>(fc_bias, nullptr);
    // GEMM2: [2048,4096] @ [4096,1024] + b2 -> out (fp32)
    gemm_mma<false><<<dim3(NEMBD / 128, TOKENS / 128, NEXP), 256, SMEM_BYTES>>>(proj_bias, out);
}

// round 15
// speedup vs baseline: 1.0060x; 1.0060x over previous
#include <cuda_runtime.h>
#include <cuda_fp16.h>
#include <math.h>
#include <stdint.h>

#define NEXP   8
#define TOKENS 2048
#define NEMBD  1024
#define DFF    4096

// ---------------- device scratch (no runtime allocation) ----------------
__device__ __half g_x16[(size_t)NEXP * TOKENS * NEMBD];
__device__ __half g_w1[(size_t)NEXP * DFF * NEMBD];   // [e][N=DFF][K=NEMBD]
__device__ __half g_w2[(size_t)NEXP * NEMBD * DFF];   // [e][N=NEMBD][K=DFF]
__device__ __half g_h16[(size_t)NEXP * TOKENS * DFF]; // hidden (post-GELU)

// ---------------- helpers ----------------
__device__ __forceinline__ uint32_t smem_to_u32(const void* p) {
    uint32_t a;
    asm("{ .reg .u64 t; cvta.to.shared.u64 t, %1; cvt.u32.u64 %0, t; }" : "=r"(a) : "l"(p));
    return a;
}
__device__ __forceinline__ void cp_async16(uint32_t saddr, const void* gaddr) {
    asm volatile("cp.async.cg.shared.global [%0], [%1], 16;" :: "r"(saddr), "l"(gaddr));
}
#define CP_COMMIT() asm volatile("cp.async.commit_group;" ::: "memory")
#define CP_WAIT(n)  asm volatile("cp.async.wait_group %0;" :: "n"(n) : "memory")

__device__ __forceinline__ void ldsm_x4(uint32_t* r, uint32_t addr) {
    asm volatile("ldmatrix.sync.aligned.m8n8.x4.shared.b16 {%0,%1,%2,%3}, [%4];"
        : "=r"(r[0]), "=r"(r[1]), "=r"(r[2]), "=r"(r[3]) : "r"(addr));
}
__device__ __forceinline__ void mma_fp16(float* d, const uint32_t* a, const uint32_t* b) {
    asm volatile(
        "mma.sync.aligned.m16n8k16.row.col.f32.f16.f16.f32 "
        "{%0,%1,%2,%3}, {%4,%5,%6,%7}, {%8,%9}, {%0,%1,%2,%3};"
        : "+f"(d[0]), "+f"(d[1]), "+f"(d[2]), "+f"(d[3])
        : "r"(a[0]), "r"(a[1]), "r"(a[2]), "r"(a[3]), "r"(b[0]), "r"(b[1]));
}

__device__ __forceinline__ float gelu_exact(float x) {
    return 0.5f * x * (1.0f + erff(x * 0.70710678118654752440f));
}

// ---------------- pre-pass: convert x -> fp16 ----------------
__global__ __launch_bounds__(256) void conv_x(const float* __restrict__ x) {
    const size_t n4 = (size_t)NEXP * TOKENS * NEMBD / 4;
    const float4* in = reinterpret_cast<const float4*>(x);
    for (size_t i = blockIdx.x * 256ull + threadIdx.x; i < n4; i += (size_t)gridDim.x * 256) {
        float4 v = in[i];
        __half2 a = __halves2half2(__float2half_rn(v.x), __float2half_rn(v.y));
        __half2 b = __halves2half2(__float2half_rn(v.z), __float2half_rn(v.w));
        reinterpret_cast<uint2*>(g_x16)[i] =
            make_uint2(*reinterpret_cast<uint32_t*>(&a), *reinterpret_cast<uint32_t*>(&b));
    }
}

// ---------------- pre-pass: convert + transpose weights ----------------
template<int W>
__global__ __launch_bounds__(256) void conv_transpose(const float* __restrict__ in) {
    constexpr int R = (W == 1) ? NEMBD : DFF;
    constexpr int C = (W == 1) ? DFF : NEMBD;
    __half* oh = (W == 1) ? g_w1 : g_w2;
    __shared__ float t[32][33];
    const int e = blockIdx.z;
    const float* src = in + (size_t)e * R * C;
    __half* dh = oh + (size_t)e * R * C;
    const int c0 = blockIdx.x * 32, r0 = blockIdx.y * 32;
    const int tx = threadIdx.x & 31, ty = threadIdx.x >> 5;   // 32 x 8
    #pragma unroll
    for (int j = 0; j < 4; ++j)
        t[ty + j * 8][tx] = src[(size_t)(r0 + ty + j * 8) * C + c0 + tx];
    __syncthreads();
    #pragma unroll
    for (int j = 0; j < 4; ++j) {
        float v = t[tx][ty + j * 8];                     // in[r0+tx][c0+ty+j*8]
        size_t o = (size_t)(c0 + ty + j * 8) * R + r0 + tx;
        dh[o] = __float2half_rn(v);
    }
}

// ---------------- mma.sync grouped GEMM, plain fp16 ----------------
// CTA tile 128(m) x 128(n), BK=64, 256 threads = 8 warps as 2(m) x 4(n),
// warp tile 64x32. 3-stage cp.async pipeline, 2 CTAs/SM.
// Register-level software pipeline: B fragments double-buffered across ks;
// next-ks fragments prefetched during the last MMA batch of the current ks.
template<bool DO_GELU>
__global__ __launch_bounds__(256, 2) void gemm_mma(const float* __restrict__ bias_all,
                                                   float* __restrict__ Cf) {
    constexpr int M = TOKENS;
    constexpr int N = DO_GELU ? DFF : NEMBD;
    constexpr int K = DO_GELU ? NEMBD : DFF;
    constexpr int NC = K / 64;             // k-chunks of 64
    constexpr int ROWB = 144;              // bytes per smem row (64 fp16 + 16 pad)
    constexpr int A_TILE = 128 * ROWB;     // 18432
    constexpr int B_TILE = 128 * ROWB;     // 18432
    constexpr int STAGE = A_TILE + B_TILE; // 36864
    constexpr int NSTAGE = 3;

    const __half* Abase = DO_GELU ? g_x16 : g_h16;
    const __half* Bbase = DO_GELU ? g_w1 : g_w2;

    extern __shared__ __align__(1024) char smem[];
    const uint32_t sbase = smem_to_u32(smem);

    const int tid = threadIdx.x;
    const int wid = tid >> 5, lane = tid & 31;
    const int e = blockIdx.z;
    const int m0 = blockIdx.y * 128, n0 = blockIdx.x * 128;

    const __half* A = Abase + (size_t)e * M * K;
    const __half* B = Bbase + (size_t)e * N * K;
    const float* bias = bias_all + (size_t)e * N;

    // warp tile: 64(m) x 32(n); warps arranged 2(m) x 4(n)
    const int wm = (wid >> 2) * 64;
    const int wn = (wid & 3) * 32;

    float acc[4][4][4];
    #pragma unroll
    for (int i = 0; i < 4; ++i)
        #pragma unroll
        for (int j = 0; j < 4; ++j)
            #pragma unroll
            for (int q = 0; q < 4; ++q) acc[i][j][q] = 0.0f;

    // ---- loader: 2 base pointers, compile-time row offsets ----
    const uint32_t l_row = (uint32_t)tid >> 3;       // 0..31
    const uint32_t l_ch  = (uint32_t)tid & 7;        // 0..7
    const uint32_t l_so  = l_row * ROWB + l_ch * 16; // smem offset within tile
    const __half* a_base = A + (size_t)(m0 + l_row) * K + l_ch * 8;
    const __half* b_base = B + (size_t)(n0 + l_row) * K + l_ch * 8;

    auto load_stage = [&](int s) {
        const uint32_t sb = sbase + s * STAGE;
        #pragma unroll
        for (int it = 0; it < 4; ++it)
            cp_async16(sb + l_so + (uint32_t)(it * 32 * ROWB), a_base + (size_t)(it * 32) * K);
        #pragma unroll
        for (int it = 0; it < 4; ++it)
            cp_async16(sb + A_TILE + l_so + (uint32_t)(it * 32 * ROWB), b_base + (size_t)(it * 32) * K);
        CP_COMMIT();
        a_base += 64; b_base += 64;
    };

    load_stage(0);
    load_stage(1);

    // per-lane ldmatrix address components
    const uint32_t a_off = (uint32_t)((wm + (lane & 15)) * ROWB + (lane >> 4) * 16);
    const uint32_t b_off = (uint32_t)((wn + (lane & 7) + ((lane >> 4) << 3)) * ROWB + ((lane >> 3) & 1) * 16);

    int s = 0;
    for (int c = 0; c < NC; ++c) {
        if (c + 1 < NC) { CP_WAIT(1); } else { CP_WAIT(0); }
        __syncthreads();
        if (c + 2 < NC) {
            int s2 = s + 2; if (s2 >= NSTAGE) s2 -= NSTAGE;
            load_stage(s2);
        }

        const uint32_t sb = sbase + s * STAGE;
        if (++s == NSTAGE) s = 0;
        const uint32_t a_sm = sb + a_off;
        const uint32_t b_sm = sb + A_TILE + b_off;

        // fragment pipeline registers
        uint32_t bf[2][2][4];   // [ks parity][nt2][4]
        uint32_t af[2][4];      // [mt parity][4]

        // chunk head: fragments for ks=0
        ldsm_x4(bf[0][0], b_sm);
        ldsm_x4(bf[0][1], b_sm + (uint32_t)(16 * ROWB));
        ldsm_x4(af[0], a_sm);

        #pragma unroll
        for (int ks = 0; ks < 4; ++ks) {
            const int cur = ks & 1;
            const uint32_t kso = (uint32_t)(ks * 32);
            #pragma unroll
            for (int mt = 0; mt < 4; ++mt) {
                const int abuf = mt & 1;
                // prefetch next fragments before this MMA batch
                if (mt < 3) {
                    ldsm_x4(af[abuf ^ 1], a_sm + kso + (uint32_t)((mt + 1) * 16 * ROWB));
                } else if (ks < 3) {
                    const uint32_t kso_n = kso + 32;
                    ldsm_x4(bf[cur ^ 1][0], b_sm + kso_n);
                    ldsm_x4(bf[cur ^ 1][1], b_sm + kso_n + (uint32_t)(16 * ROWB));
                    ldsm_x4(af[abuf ^ 1], a_sm + kso_n);   // af[0] for next ks, mt=0
                }
                #pragma unroll
                for (int nt = 0; nt < 4; ++nt)
                    mma_fp16(acc[mt][nt], af[abuf], &bf[cur][nt >> 1][(nt & 1) * 2]);
            }
        }
    }

    // ---------------- epilogue ----------------
    const int groupID = lane >> 2, tig = lane & 3;
    #pragma unroll
    for (int mt = 0; mt < 4; ++mt) {
        const int r0g = m0 + wm + mt * 16 + groupID;
        #pragma unroll
        for (int nt = 0; nt < 4; ++nt) {
            const int col = n0 + wn + nt * 8 + tig * 2;
            const float2 bv = *reinterpret_cast<const float2*>(&bias[col]);
            float v0 = acc[mt][nt][0] + bv.x;
            float v1 = acc[mt][nt][1] + bv.y;
            float v2 = acc[mt][nt][2] + bv.x;
            float v3 = acc[mt][nt][3] + bv.y;
            if (DO_GELU) {
                v0 = gelu_exact(v0); v1 = gelu_exact(v1);
                v2 = gelu_exact(v2); v3 = gelu_exact(v3);
                const size_t o0 = ((size_t)e * M + r0g) * N + col;
                const size_t o1 = ((size_t)e * M + r0g + 8) * N + col;
                *reinterpret_cast<__half2*>(g_h16 + o0) =
                    __halves2half2(__float2half_rn(v0), __float2half_rn(v1));
                *reinterpret_cast<__half2*>(g_h16 + o1) =
                    __halves2half2(__float2half_rn(v2), __float2half_rn(v3));
            } else {
                const size_t o0 = ((size_t)e * M + r0g) * N + col;
                const size_t o1 = ((size_t)e * M + r0g + 8) * N + col;
                *reinterpret_cast<float2*>(Cf + o0) = make_float2(v0, v1);
                *reinterpret_cast<float2*>(Cf + o1) = make_float2(v2, v3);
            }
        }
    }
}

// ---------------- launch ----------------
extern "C" void kernel_launch(void* const* d_in, const int* in_sizes, int n_in,
                              void* d_out, int out_size) {
    const float* x         = (const float*)d_in[0];
    const float* c_fc      = (const float*)d_in[1];
    const float* c_proj    = (const float*)d_in[2];
    const float* fc_bias   = (const float*)d_in[3];
    const float* proj_bias = (const float*)d_in[4];
    float* out = (float*)d_out;

    constexpr int SMEM_BYTES = 3 * 36864;   // 110592 per CTA, 2 CTAs/SM
    cudaFuncSetAttribute(gemm_mma<true>,  cudaFuncAttributeMaxDynamicSharedMemorySize, SMEM_BYTES);
    cudaFuncSetAttribute(gemm_mma<false>, cudaFuncAttributeMaxDynamicSharedMemorySize, SMEM_BYTES);

    // pre-passes
    conv_x<<<4096, 256>>>(x);
    conv_transpose<1><<<dim3(DFF / 32, NEMBD / 32, NEXP), 256>>>(c_fc);
    conv_transpose<2><<<dim3(NEMBD / 32, DFF / 32, NEXP), 256>>>(c_proj);

    // GEMM1: [2048,1024] @ [1024,4096] + b1, gelu -> h (fp16)
    gemm_mma<true><<<dim3(DFF / 128, TOKENS / 128, NEXP), 256, SMEM_BYTES>>>(fc_bias, nullptr);
    // GEMM2: [2048,4096] @ [4096,1024] + b2 -> out (fp32)
    gemm_mma<false><<<dim3(NEMBD / 128, TOKENS / 128, NEXP), 256, SMEM_BYTES>>>(proj_bias, out);
}

// round 16
// speedup vs baseline: 1.0182x; 1.0121x over previous
#include <cuda_runtime.h>
#include <cuda_fp16.h>
#include <math.h>
#include <stdint.h>

#define NEXP   8
#define TOKENS 2048
#define NEMBD  1024
#define DFF    4096

// ---------------- device scratch (no runtime allocation) ----------------
__device__ __half g_x16[(size_t)NEXP * TOKENS * NEMBD];
__device__ __half g_w1[(size_t)NEXP * DFF * NEMBD];   // [e][N=DFF][K=NEMBD]
__device__ __half g_w2[(size_t)NEXP * NEMBD * DFF];   // [e][N=NEMBD][K=DFF]
__device__ __half g_h16[(size_t)NEXP * TOKENS * DFF]; // hidden (post-GELU)

// ---------------- helpers ----------------
__device__ __forceinline__ uint32_t smem_to_u32(const void* p) {
    uint32_t a;
    asm("{ .reg .u64 t; cvta.to.shared.u64 t, %1; cvt.u32.u64 %0, t; }" : "=r"(a) : "l"(p));
    return a;
}
__device__ __forceinline__ void cp_async16(uint32_t saddr, const void* gaddr) {
    asm volatile("cp.async.cg.shared.global [%0], [%1], 16;" :: "r"(saddr), "l"(gaddr));
}
#define CP_COMMIT() asm volatile("cp.async.commit_group;" ::: "memory")
#define CP_WAIT(n)  asm volatile("cp.async.wait_group %0;" :: "n"(n) : "memory")

__device__ __forceinline__ void ldsm_x4(uint32_t* r, uint32_t addr) {
    asm volatile("ldmatrix.sync.aligned.m8n8.x4.shared.b16 {%0,%1,%2,%3}, [%4];"
        : "=r"(r[0]), "=r"(r[1]), "=r"(r[2]), "=r"(r[3]) : "r"(addr));
}
__device__ __forceinline__ void mma_fp16(float* d, const uint32_t* a, const uint32_t* b) {
    asm volatile(
        "mma.sync.aligned.m16n8k16.row.col.f32.f16.f16.f32 "
        "{%0,%1,%2,%3}, {%4,%5,%6,%7}, {%8,%9}, {%0,%1,%2,%3};"
        : "+f"(d[0]), "+f"(d[1]), "+f"(d[2]), "+f"(d[3])
        : "r"(a[0]), "r"(a[1]), "r"(a[2]), "r"(a[3]), "r"(b[0]), "r"(b[1]));
}

__device__ __forceinline__ float gelu_exact(float x) {
    return 0.5f * x * (1.0f + erff(x * 0.70710678118654752440f));
}

// ---------------- pre-pass: convert x -> fp16 ----------------
__global__ __launch_bounds__(256) void conv_x(const float* __restrict__ x) {
    const size_t n4 = (size_t)NEXP * TOKENS * NEMBD / 4;
    const float4* in = reinterpret_cast<const float4*>(x);
    for (size_t i = blockIdx.x * 256ull + threadIdx.x; i < n4; i += (size_t)gridDim.x * 256) {
        float4 v = in[i];
        __half2 a = __halves2half2(__float2half_rn(v.x), __float2half_rn(v.y));
        __half2 b = __halves2half2(__float2half_rn(v.z), __float2half_rn(v.w));
        reinterpret_cast<uint2*>(g_x16)[i] =
            make_uint2(*reinterpret_cast<uint32_t*>(&a), *reinterpret_cast<uint32_t*>(&b));
    }
}

// ---------------- pre-pass: convert + transpose weights ----------------
template<int W>
__global__ __launch_bounds__(256) void conv_transpose(const float* __restrict__ in) {
    constexpr int R = (W == 1) ? NEMBD : DFF;
    constexpr int C = (W == 1) ? DFF : NEMBD;
    __half* oh = (W == 1) ? g_w1 : g_w2;
    __shared__ float t[32][33];
    const int e = blockIdx.z;
    const float* src = in + (size_t)e * R * C;
    __half* dh = oh + (size_t)e * R * C;
    const int c0 = blockIdx.x * 32, r0 = blockIdx.y * 32;
    const int tx = threadIdx.x & 31, ty = threadIdx.x >> 5;   // 32 x 8
    #pragma unroll
    for (int j = 0; j < 4; ++j)
        t[ty + j * 8][tx] = src[(size_t)(r0 + ty + j * 8) * C + c0 + tx];
    __syncthreads();
    #pragma unroll
    for (int j = 0; j < 4; ++j) {
        float v = t[tx][ty + j * 8];                     // in[r0+tx][c0+ty+j*8]
        size_t o = (size_t)(c0 + ty + j * 8) * R + r0 + tx;
        dh[o] = __float2half_rn(v);
    }
}

// ---------------- mma.sync grouped GEMM, plain fp16 (R13 body) ----------------
// CTA tile 128(m) x 128(n), BK=64, 256 threads = 8 warps as 2(m) x 4(n),
// warp tile 64x32. 3-stage cp.async pipeline, 2 CTAs/SM.
template<bool DO_GELU>
__global__ __launch_bounds__(256, 2) void gemm_mma(const float* __restrict__ bias_all,
                                                   float* __restrict__ Cf) {
    constexpr int M = TOKENS;
    constexpr int N = DO_GELU ? DFF : NEMBD;
    constexpr int K = DO_GELU ? NEMBD : DFF;
    constexpr int NC = K / 64;             // k-chunks of 64
    constexpr int ROWB = 144;              // bytes per smem row (64 fp16 + 16 pad)
    constexpr int A_TILE = 128 * ROWB;     // 18432
    constexpr int B_TILE = 128 * ROWB;     // 18432
    constexpr int STAGE = A_TILE + B_TILE; // 36864
    constexpr int NSTAGE = 3;

    const __half* Abase = DO_GELU ? g_x16 : g_h16;
    const __half* Bbase = DO_GELU ? g_w1 : g_w2;

    extern __shared__ __align__(1024) char smem[];
    const uint32_t sbase = smem_to_u32(smem);

    const int tid = threadIdx.x;
    const int wid = tid >> 5, lane = tid & 31;
    const int e = blockIdx.z;
    const int m0 = blockIdx.y * 128, n0 = blockIdx.x * 128;

    const __half* A = Abase + (size_t)e * M * K;
    const __half* B = Bbase + (size_t)e * N * K;
    const float* bias = bias_all + (size_t)e * N;

    // warp tile: 64(m) x 32(n); warps arranged 2(m) x 4(n)
    const int wm = (wid >> 2) * 64;
    const int wn = (wid & 3) * 32;

    float acc[4][4][4];
    #pragma unroll
    for (int i = 0; i < 4; ++i)
        #pragma unroll
        for (int j = 0; j < 4; ++j)
            #pragma unroll
            for (int q = 0; q < 4; ++q) acc[i][j][q] = 0.0f;

    // ---- hoisted loader state ----
    const uint32_t l_row = (uint32_t)tid >> 3;       // 0..31
    const uint32_t l_ch  = (uint32_t)tid & 7;        // 0..7
    const uint32_t l_so  = l_row * ROWB + l_ch * 16; // smem offset within tile
    const __half* aptr[4];
    const __half* bptr[4];
    #pragma unroll
    for (int it = 0; it < 4; ++it) {
        aptr[it] = A + (size_t)(m0 + l_row + it * 32) * K + l_ch * 8;
        bptr[it] = B + (size_t)(n0 + l_row + it * 32) * K + l_ch * 8;
    }

    auto load_stage = [&](int s) {
        const uint32_t sb = sbase + s * STAGE;
        #pragma unroll
        for (int it = 0; it < 4; ++it)
            cp_async16(sb + l_so + (uint32_t)(it * 32 * ROWB), aptr[it]);
        #pragma unroll
        for (int it = 0; it < 4; ++it)
            cp_async16(sb + A_TILE + l_so + (uint32_t)(it * 32 * ROWB), bptr[it]);
        CP_COMMIT();
        #pragma unroll
        for (int it = 0; it < 4; ++it) { aptr[it] += 64; bptr[it] += 64; }
    };

    load_stage(0);
    load_stage(1);

    // per-lane ldmatrix address components
    const uint32_t a_off = (uint32_t)((wm + (lane & 15)) * ROWB + (lane >> 4) * 16);
    const uint32_t b_off = (uint32_t)((wn + (lane & 7) + ((lane >> 4) << 3)) * ROWB + ((lane >> 3) & 1) * 16);

    int s = 0;
    for (int c = 0; c < NC; ++c) {
        if (c + 1 < NC) { CP_WAIT(1); } else { CP_WAIT(0); }
        __syncthreads();
        if (c + 2 < NC) {
            int s2 = s + 2; if (s2 >= NSTAGE) s2 -= NSTAGE;
            load_stage(s2);
        }

        const uint32_t sb = sbase + s * STAGE;
        if (++s == NSTAGE) s = 0;
        #pragma unroll
        for (int ks = 0; ks < 4; ++ks) {
            const uint32_t kso = (uint32_t)(ks * 32);
            uint32_t bf[2][4];
            #pragma unroll
            for (int nt2 = 0; nt2 < 2; ++nt2)
                ldsm_x4(bf[nt2], sb + A_TILE + b_off + kso + (uint32_t)(nt2 * 16 * ROWB));
            // A-fragment double buffer across mt
            uint32_t af[2][4];
            ldsm_x4(af[0], sb + a_off + kso);
            #pragma unroll
            for (int mt = 0; mt < 4; ++mt) {
                if (mt + 1 < 4)
                    ldsm_x4(af[(mt + 1) & 1], sb + a_off + kso + (uint32_t)((mt + 1) * 16 * ROWB));
                #pragma unroll
                for (int nt = 0; nt < 4; ++nt)
                    mma_fp16(acc[mt][nt], af[mt & 1], &bf[nt >> 1][(nt & 1) * 2]);
            }
        }
    }

    // ---------------- epilogue ----------------
    const int groupID = lane >> 2, tig = lane & 3;
    #pragma unroll
    for (int mt = 0; mt < 4; ++mt) {
        const int r0g = m0 + wm + mt * 16 + groupID;
        #pragma unroll
        for (int nt = 0; nt < 4; ++nt) {
            const int col = n0 + wn + nt * 8 + tig * 2;
            const float2 bv = *reinterpret_cast<const float2*>(&bias[col]);
            float v0 = acc[mt][nt][0] + bv.x;
            float v1 = acc[mt][nt][1] + bv.y;
            float v2 = acc[mt][nt][2] + bv.x;
            float v3 = acc[mt][nt][3] + bv.y;
            if (DO_GELU) {
                v0 = gelu_exact(v0); v1 = gelu_exact(v1);
                v2 = gelu_exact(v2); v3 = gelu_exact(v3);
                const size_t o0 = ((size_t)e * M + r0g) * N + col;
                const size_t o1 = ((size_t)e * M + r0g + 8) * N + col;
                *reinterpret_cast<__half2*>(g_h16 + o0) =
                    __halves2half2(__float2half_rn(v0), __float2half_rn(v1));
                *reinterpret_cast<__half2*>(g_h16 + o1) =
                    __halves2half2(__float2half_rn(v2), __float2half_rn(v3));
            } else {
                const size_t o0 = ((size_t)e * M + r0g) * N + col;
                const size_t o1 = ((size_t)e * M + r0g + 8) * N + col;
                *reinterpret_cast<float2*>(Cf + o0) = make_float2(v0, v1);
                *reinterpret_cast<float2*>(Cf + o1) = make_float2(v2, v3);
            }
        }
    }
}

// ---------------- launch (graph-forked prepasses) ----------------
extern "C" void kernel_launch(void* const* d_in, const int* in_sizes, int n_in,
                              void* d_out, int out_size) {
    const float* x         = (const float*)d_in[0];
    const float* c_fc      = (const float*)d_in[1];
    const float* c_proj    = (const float*)d_in[2];
    const float* fc_bias   = (const float*)d_in[3];
    const float* proj_bias = (const float*)d_in[4];
    float* out = (float*)d_out;

    constexpr int SMEM_BYTES = 3 * 36864;   // 110592 per CTA, 2 CTAs/SM
    cudaFuncSetAttribute(gemm_mma<true>,  cudaFuncAttributeMaxDynamicSharedMemorySize, SMEM_BYTES);
    cudaFuncSetAttribute(gemm_mma<false>, cudaFuncAttributeMaxDynamicSharedMemorySize, SMEM_BYTES);

    // one-time side-stream / event resources (created on first, uncaptured call)
    static cudaStream_t s_w1 = nullptr, s_w2 = nullptr;
    static cudaEvent_t ev_root = nullptr, ev_w1 = nullptr, ev_w2 = nullptr;
    if (s_w1 == nullptr) {
        cudaStreamCreateWithFlags(&s_w1, cudaStreamNonBlocking);
        cudaStreamCreateWithFlags(&s_w2, cudaStreamNonBlocking);
        cudaEventCreateWithFlags(&ev_root, cudaEventDisableTiming);
        cudaEventCreateWithFlags(&ev_w1,   cudaEventDisableTiming);
        cudaEventCreateWithFlags(&ev_w2,   cudaEventDisableTiming);
    }

    cudaStream_t s0 = 0;   // harness capture stream (legacy default)

    // fork: w1 and w2 conversions run on side streams; x conversion on s0
    cudaEventRecord(ev_root, s0);
    cudaStreamWaitEvent(s_w1, ev_root, 0);
    cudaStreamWaitEvent(s_w2, ev_root, 0);

    conv_transpose<1><<<dim3(DFF / 32, NEMBD / 32, NEXP), 256, 0, s_w1>>>(c_fc);
    cudaEventRecord(ev_w1, s_w1);

    conv_transpose<2><<<dim3(NEMBD / 32, DFF / 32, NEXP), 256, 0, s_w2>>>(c_proj);
    cudaEventRecord(ev_w2, s_w2);

    conv_x<<<4096, 256, 0, s0>>>(x);

    // GEMM1 needs x16 + w1 (w2 conversion continues in parallel)
    cudaStreamWaitEvent(s0, ev_w1, 0);
    gemm_mma<true><<<dim3(DFF / 128, TOKENS / 128, NEXP), 256, SMEM_BYTES, s0>>>(fc_bias, nullptr);

    // GEMM2 needs h (s0 order) + w2 (join)
    cudaStreamWaitEvent(s0, ev_w2, 0);
    gemm_mma<false><<<dim3(NEMBD / 128, TOKENS / 128, NEXP), 256, SMEM_BYTES, s0>>>(proj_bias, out);
}